// round 7
// baseline (speedup 1.0000x reference)
#include <cuda_runtime.h>

#define N_MAX   100000
#define HID     32

// Precomputed-parameter layout (floats) in g_P:
//   [0..36)   A[h][i][j]   4 heads x 3x3 score quadratic forms
//   [36..48)  B[h][i]      4 heads x 3   score linear terms
//   [48..52)  C[h]         4 heads       score constants
//   [52..64)  pad
//   [64..576) MM[16][32]   row t=h*4+i : (Wv_h @ Wout_h) rows (i<3), bv_h @ Wout_h (i==3)
#define OFF_A   0
#define OFF_B   36
#define OFF_C   48
#define OFF_MM  64
#define P_SIZE  576
#define P_EDGE  64          // edge kernel only needs A/B/C

__device__ float g_P[P_SIZE];
__device__ float g_wacc[16 * N_MAX];   // layout [t][node] — spreads one edge's 16 reds
__device__ int   g_idx64;              // 1 if edge_index is int64, 0 if int32

// ---------------------------------------------------------------------------
// Probe: decide whether edge_index is int64 or int32 from the data.
// Real int64 indices all lie in [0, N); int32 data misread as int64 packs two
// random indices per word -> astronomically out of range almost surely.
// ---------------------------------------------------------------------------
__global__ void probe_kernel(const void* __restrict__ ei, int E, int N) {
    if (threadIdx.x == 0) {
        const long long* p = (const long long*)ei;
        int n = E < 256 ? E : 256;
        int ok = 1;
        for (int i = 0; i < n; i++) {
            long long v = p[i];
            if (v < 0 || v >= (long long)N) { ok = 0; break; }
        }
        g_idx64 = ok;
    }
}

// ---------------------------------------------------------------------------
// Setup: fold Wq/Wk/bq/bk into per-head 3x3 quadratic score forms,
//        fold Wv/bv @ Wout into MM[16][32].
// ---------------------------------------------------------------------------
__global__ void setup_kernel(const float* __restrict__ Wq, const float* __restrict__ bq,
                             const float* __restrict__ Wk, const float* __restrict__ bk,
                             const float* __restrict__ Wv, const float* __restrict__ bv,
                             const float* __restrict__ Wout) {
    int t = threadIdx.x;
    if (t < 512) {
        int row = t >> 5, j = t & 31;
        int h = row >> 2, i = row & 3;
        int base = h * 32;
        float s = 0.f;
        if (i < 3) {
            #pragma unroll 4
            for (int d = 0; d < 32; d++)
                s = fmaf(Wv[i * 128 + base + d], Wout[(base + d) * 32 + j], s);
        } else {
            #pragma unroll 4
            for (int d = 0; d < 32; d++)
                s = fmaf(bv[base + d], Wout[(base + d) * 32 + j], s);
        }
        g_P[OFF_MM + row * 32 + j] = s;
    } else if (t < 548) {
        int a = t - 512;
        int h = a / 9, rem = a % 9;
        int i = rem / 3, j = rem % 3;
        int base = h * 32;
        float s = 0.f;
        for (int d = 0; d < 32; d++)
            s = fmaf(Wq[i * 128 + base + d], Wk[j * 128 + base + d], s);
        g_P[OFF_A + a] = s;
    } else if (t < 560) {
        int a = t - 548;
        int h = a / 3, i = a % 3;
        int base = h * 32;
        float s = 0.f;
        for (int d = 0; d < 32; d++) {
            s = fmaf(Wq[i * 128 + base + d], bk[base + d], s);
            s = fmaf(Wk[i * 128 + base + d], bq[base + d], s);
        }
        g_P[OFF_B + a] = s;
    } else if (t < 564) {
        int h = t - 560;
        int base = h * 32;
        float s = 0.f;
        for (int d = 0; d < 32; d++)
            s = fmaf(bq[base + d], bk[base + d], s);
        g_P[OFF_C + h] = s;
    } else if (t < 576) {
        g_P[52 + (t - 564)] = 0.f;   // pad region
    }
}

// ---------------------------------------------------------------------------
// Zero the 16-coefficient node accumulators (every launch).
// ---------------------------------------------------------------------------
__global__ void zero_kernel(int tot) {
    int i = blockIdx.x * blockDim.x + threadIdx.x;
    if (i < tot) g_wacc[i] = 0.f;
}

// ---------------------------------------------------------------------------
// Edge kernel: 1 thread = 1 edge.
//   rel -> 4 head scores (3x3 quadratic forms) -> softmax ->
//   16 blend coeffs w[h*4+i] = attn_h * {rx,ry,rz,1} -> 16 scalar red.add
// ---------------------------------------------------------------------------
__global__ void __launch_bounds__(256) edge_kernel(const float* __restrict__ pos,
                                                   const void* __restrict__ ei_raw,
                                                   int E, int N) {
    __shared__ float sP[P_EDGE];
    if (threadIdx.x < P_EDGE) sP[threadIdx.x] = g_P[threadIdx.x];
    __syncthreads();

    int e = blockIdx.x * blockDim.x + threadIdx.x;
    if (e >= E) return;

    int r, c;
    if (g_idx64) {
        const long long* ei = (const long long*)ei_raw;
        r = (int)ei[e];
        c = (int)ei[E + e];
    } else {
        const int* ei = (const int*)ei_raw;
        r = ei[e];
        c = ei[E + e];
    }

    float rx = pos[3 * r + 0] - pos[3 * c + 0];
    float ry = pos[3 * r + 1] - pos[3 * c + 1];
    float rz = pos[3 * r + 2] - pos[3 * c + 2];

    // scores per head: (rel^T A rel + B.rel + C) / sqrt(32)
    float s[4];
    #pragma unroll
    for (int h = 0; h < 4; h++) {
        const float* Ah = sP + OFF_A + h * 9;
        const float* Bh = sP + OFF_B + h * 3;
        float u0 = fmaf(Ah[0], rx, fmaf(Ah[1], ry, fmaf(Ah[2], rz, Bh[0])));
        float u1 = fmaf(Ah[3], rx, fmaf(Ah[4], ry, fmaf(Ah[5], rz, Bh[1])));
        float u2 = fmaf(Ah[6], rx, fmaf(Ah[7], ry, fmaf(Ah[8], rz, Bh[2])));
        s[h] = fmaf(rx, u0, fmaf(ry, u1, fmaf(rz, u2, sP[OFF_C + h])))
               * 0.17677669529663687f;   // 1/sqrt(32)
    }

    // softmax over 4 heads
    float m  = fmaxf(fmaxf(s[0], s[1]), fmaxf(s[2], s[3]));
    float e0 = __expf(s[0] - m);
    float e1 = __expf(s[1] - m);
    float e2 = __expf(s[2] - m);
    float e3 = __expf(s[3] - m);
    float inv = 1.f / (e0 + e1 + e2 + e3);
    float at[4] = {e0 * inv, e1 * inv, e2 * inv, e3 * inv};

    // scatter 16 blend coefficients; [t][node] layout spreads lines/slices
    #pragma unroll
    for (int h = 0; h < 4; h++) {
        atomicAdd(&g_wacc[(h * 4 + 0) * N + c], at[h] * rx);
        atomicAdd(&g_wacc[(h * 4 + 1) * N + c], at[h] * ry);
        atomicAdd(&g_wacc[(h * 4 + 2) * N + c], at[h] * rz);
        atomicAdd(&g_wacc[(h * 4 + 3) * N + c], at[h]);      // also the edge count
    }
}

// ---------------------------------------------------------------------------
// Node kernel: 1 warp = 1 node, lane = output channel.
//   x = (w16 @ MM)/cnt + bout, warp-shfl LayerNorm, SiLU.
//   cnt = sum of accumulated attn weights = edge count (softmax sums to 1).
// ---------------------------------------------------------------------------
__global__ void __launch_bounds__(256) node_kernel(const float* __restrict__ bout,
                                                   const float* __restrict__ gamma,
                                                   const float* __restrict__ beta,
                                                   float* __restrict__ out, int N) {
    __shared__ float sMM[512];
    for (int t = threadIdx.x; t < 512; t += blockDim.x)
        sMM[t] = g_P[OFF_MM + t];
    __syncthreads();

    int gt = blockIdx.x * blockDim.x + threadIdx.x;
    int n = gt >> 5;
    int j = gt & 31;
    if (n >= N) return;

    // lanes 0..15 hold w[lane]; broadcast through shfl
    float wv = (j < 16) ? g_wacc[j * N + n] : 0.f;

    float acc = 0.f;
    float cnt = 0.f;
    #pragma unroll
    for (int t = 0; t < 16; t++) {
        float wt = __shfl_sync(0xffffffffu, wv, t);
        acc = fmaf(wt, sMM[t * 32 + j], acc);
        if ((t & 3) == 3) cnt += wt;
    }

    float x = acc / fmaxf(cnt, 1.0f) + bout[j];

    float mu = x;
    #pragma unroll
    for (int o = 16; o; o >>= 1) mu += __shfl_xor_sync(0xffffffffu, mu, o);
    mu *= 0.03125f;

    float d = x - mu;
    float v = d * d;
    #pragma unroll
    for (int o = 16; o; o >>= 1) v += __shfl_xor_sync(0xffffffffu, v, o);
    v *= 0.03125f;

    float y = fmaf(d * rsqrtf(v + 1e-5f), gamma[j], beta[j]);
    out[n * HID + j] = y / (1.f + __expf(-y));   // SiLU
}

// ---------------------------------------------------------------------------
extern "C" void kernel_launch(void* const* d_in, const int* in_sizes, int n_in,
                              void* d_out, int out_size) {
    const float* pos   = (const float*)d_in[0];
    const void*  ei    = d_in[1];
    const float* Wq    = (const float*)d_in[2];
    const float* bq    = (const float*)d_in[3];
    const float* Wk    = (const float*)d_in[4];
    const float* bk    = (const float*)d_in[5];
    const float* Wv    = (const float*)d_in[6];
    const float* bv    = (const float*)d_in[7];
    const float* Wout  = (const float*)d_in[8];
    const float* bout  = (const float*)d_in[9];
    const float* gamma = (const float*)d_in[10];
    const float* beta  = (const float*)d_in[11];
    float*       out   = (float*)d_out;

    int N = in_sizes[0] / 3;    // 100000
    int E = in_sizes[1] / 2;    // 500000
    int wtot = 16 * N;

    probe_kernel<<<1, 32>>>(ei, E, N);
    setup_kernel<<<1, 576>>>(Wq, bq, Wk, bk, Wv, bv, Wout);
    zero_kernel<<<(wtot + 255) / 256, 256>>>(wtot);
    edge_kernel<<<(E + 255) / 256, 256>>>(pos, ei, E, N);
    node_kernel<<<(N * HID + 255) / 256, 256>>>(bout, gamma, beta, out, N);
}

// round 9
// speedup vs baseline: 1.7735x; 1.7735x over previous
#include <cuda_runtime.h>

#define N_MAX   100000
#define HID     32

// Precomputed-parameter layout (floats) in g_P:
//   [0..36)   A[h][i][j]   4 heads x 3x3 score quadratic forms
//   [36..48)  B[h][i]      4 heads x 3   score linear terms
//   [48..52)  C[h]         4 heads       score constants
//   [52..64)  pad
//   [64..576) MM[16][32]   row t=h*4+i : (Wv_h @ Wout_h) rows (i<3), bv_h @ Wout_h (i==3)
#define OFF_A   0
#define OFF_B   36
#define OFF_C   48
#define OFF_MM  64
#define P_SIZE  576
#define P_EDGE  64          // edge kernel only needs A/B/C

__device__ float  g_P[P_SIZE];
__device__ float4 g_wacc[4 * N_MAX];   // [node][head] : (sum aw*rx, aw*ry, aw*rz, aw)
__device__ int    g_idx64;             // 1 if edge_index is int64, 0 if int32

// ---------------------------------------------------------------------------
// Setup (block 0): fold Wq/Wk/bq/bk into per-head 3x3 quadratic score forms,
//                  fold Wv/bv @ Wout into MM[16][32].
// Probe (block 1): decide int64-vs-int32 edge_index in parallel (one pass).
// ---------------------------------------------------------------------------
__global__ void setup_kernel(const float* __restrict__ Wq, const float* __restrict__ bq,
                             const float* __restrict__ Wk, const float* __restrict__ bk,
                             const float* __restrict__ Wv, const float* __restrict__ bv,
                             const float* __restrict__ Wout,
                             const void* __restrict__ ei, int E, int N) {
    int t = threadIdx.x;

    if (blockIdx.x == 1) {
        // ---- parallel dtype probe: 256 lanes each validate one int64 slot ----
        if (t < 256) {
            int n = E < 256 ? E : 256;
            int bad = 0;
            if (t < n) {
                long long v = ((const long long*)ei)[t];
                bad = (v < 0 || v >= (long long)N) ? 1 : 0;
            }
            // reduce across the 8 warps via shared
            __shared__ int s_bad;
            if (t == 0) s_bad = 0;
            __syncthreads();
            if (__any_sync(0xffffffffu, bad) && (t & 31) == 0) atomicOr(&s_bad, 1);
            __syncthreads();
            if (t == 0) g_idx64 = s_bad ? 0 : 1;
        }
        return;
    }

    if (t < 512) {
        int row = t >> 5, j = t & 31;
        int h = row >> 2, i = row & 3;
        int base = h * 32;
        float s = 0.f;
        if (i < 3) {
            #pragma unroll 4
            for (int d = 0; d < 32; d++)
                s = fmaf(Wv[i * 128 + base + d], Wout[(base + d) * 32 + j], s);
        } else {
            #pragma unroll 4
            for (int d = 0; d < 32; d++)
                s = fmaf(bv[base + d], Wout[(base + d) * 32 + j], s);
        }
        g_P[OFF_MM + row * 32 + j] = s;
    } else if (t < 548) {
        int a = t - 512;
        int h = a / 9, rem = a % 9;
        int i = rem / 3, j = rem % 3;
        int base = h * 32;
        float s = 0.f;
        for (int d = 0; d < 32; d++)
            s = fmaf(Wq[i * 128 + base + d], Wk[j * 128 + base + d], s);
        g_P[OFF_A + a] = s;
    } else if (t < 560) {
        int a = t - 548;
        int h = a / 3, i = a % 3;
        int base = h * 32;
        float s = 0.f;
        for (int d = 0; d < 32; d++) {
            s = fmaf(Wq[i * 128 + base + d], bk[base + d], s);
            s = fmaf(Wk[i * 128 + base + d], bq[base + d], s);
        }
        g_P[OFF_B + a] = s;
    } else if (t < 564) {
        int h = t - 560;
        int base = h * 32;
        float s = 0.f;
        for (int d = 0; d < 32; d++)
            s = fmaf(bq[base + d], bk[base + d], s);
        g_P[OFF_C + h] = s;
    } else if (t < 576) {
        g_P[52 + (t - 564)] = 0.f;   // pad region
    }
}

// ---------------------------------------------------------------------------
// Zero the node accumulators (every launch), float4-wide.
// ---------------------------------------------------------------------------
__global__ void zero_kernel(int tot4) {
    int i = blockIdx.x * blockDim.x + threadIdx.x;
    if (i < tot4) g_wacc[i] = make_float4(0.f, 0.f, 0.f, 0.f);
}

// ---------------------------------------------------------------------------
// Edge kernel: 1 thread = 1 edge.
//   rel -> 4 head scores (3x3 quadratic forms) -> softmax ->
//   per head one float4 vector red: (attn*rx, attn*ry, attn*rz, attn)
// ---------------------------------------------------------------------------
__global__ void __launch_bounds__(256) edge_kernel(const float* __restrict__ pos,
                                                   const void* __restrict__ ei_raw,
                                                   int E, int N) {
    __shared__ float sP[P_EDGE];
    if (threadIdx.x < P_EDGE) sP[threadIdx.x] = g_P[threadIdx.x];
    __syncthreads();

    int e = blockIdx.x * blockDim.x + threadIdx.x;
    if (e >= E) return;

    int r, c;
    if (g_idx64) {
        const long long* ei = (const long long*)ei_raw;
        r = (int)ei[e];
        c = (int)ei[E + e];
    } else {
        const int* ei = (const int*)ei_raw;
        r = ei[e];
        c = ei[E + e];
    }

    float rx = pos[3 * r + 0] - pos[3 * c + 0];
    float ry = pos[3 * r + 1] - pos[3 * c + 1];
    float rz = pos[3 * r + 2] - pos[3 * c + 2];

    // scores per head: (rel^T A rel + B.rel + C) / sqrt(32)
    float s[4];
    #pragma unroll
    for (int h = 0; h < 4; h++) {
        const float* Ah = sP + OFF_A + h * 9;
        const float* Bh = sP + OFF_B + h * 3;
        float u0 = fmaf(Ah[0], rx, fmaf(Ah[1], ry, fmaf(Ah[2], rz, Bh[0])));
        float u1 = fmaf(Ah[3], rx, fmaf(Ah[4], ry, fmaf(Ah[5], rz, Bh[1])));
        float u2 = fmaf(Ah[6], rx, fmaf(Ah[7], ry, fmaf(Ah[8], rz, Bh[2])));
        s[h] = fmaf(rx, u0, fmaf(ry, u1, fmaf(rz, u2, sP[OFF_C + h])))
               * 0.17677669529663687f;   // 1/sqrt(32)
    }

    // softmax over 4 heads
    float m  = fmaxf(fmaxf(s[0], s[1]), fmaxf(s[2], s[3]));
    float e0 = __expf(s[0] - m);
    float e1 = __expf(s[1] - m);
    float e2 = __expf(s[2] - m);
    float e3 = __expf(s[3] - m);
    float inv = 1.f / (e0 + e1 + e2 + e3);
    float at[4] = {e0 * inv, e1 * inv, e2 * inv, e3 * inv};

    // one 16B hardware vector reduction per head
    float4* base = g_wacc + c * 4;
    #pragma unroll
    for (int h = 0; h < 4; h++)
        atomicAdd(base + h, make_float4(at[h] * rx, at[h] * ry, at[h] * rz, at[h]));
}

// ---------------------------------------------------------------------------
// Node kernel: 1 warp = 1 node, lane = output channel.
//   x = (w16 @ MM)/cnt + bout, warp-shfl LayerNorm, SiLU.
//   cnt = sum of accumulated attn weights = edge count (softmax sums to 1).
// ---------------------------------------------------------------------------
__global__ void __launch_bounds__(256) node_kernel(const float* __restrict__ bout,
                                                   const float* __restrict__ gamma,
                                                   const float* __restrict__ beta,
                                                   float* __restrict__ out, int N) {
    __shared__ float sMM[512];
    for (int t = threadIdx.x; t < 512; t += blockDim.x)
        sMM[t] = g_P[OFF_MM + t];
    __syncthreads();

    int gt = blockIdx.x * blockDim.x + threadIdx.x;
    int n = gt >> 5;
    int j = gt & 31;
    if (n >= N) return;

    // lanes 0..15 hold w[lane] (contiguous 64B per node); broadcast via shfl
    const float* wrow = (const float*)(g_wacc + n * 4);
    float wv = (j < 16) ? wrow[j] : 0.f;

    float acc = 0.f;
    float cnt = 0.f;
    #pragma unroll
    for (int t = 0; t < 16; t++) {
        float wt = __shfl_sync(0xffffffffu, wv, t);
        acc = fmaf(wt, sMM[t * 32 + j], acc);
        if ((t & 3) == 3) cnt += wt;
    }

    float x = acc / fmaxf(cnt, 1.0f) + bout[j];

    float mu = x;
    #pragma unroll
    for (int o = 16; o; o >>= 1) mu += __shfl_xor_sync(0xffffffffu, mu, o);
    mu *= 0.03125f;

    float d = x - mu;
    float v = d * d;
    #pragma unroll
    for (int o = 16; o; o >>= 1) v += __shfl_xor_sync(0xffffffffu, v, o);
    v *= 0.03125f;

    float y = fmaf(d * rsqrtf(v + 1e-5f), gamma[j], beta[j]);
    out[n * HID + j] = y / (1.f + __expf(-y));   // SiLU
}

// ---------------------------------------------------------------------------
extern "C" void kernel_launch(void* const* d_in, const int* in_sizes, int n_in,
                              void* d_out, int out_size) {
    const float* pos   = (const float*)d_in[0];
    const void*  ei    = d_in[1];
    const float* Wq    = (const float*)d_in[2];
    const float* bq    = (const float*)d_in[3];
    const float* Wk    = (const float*)d_in[4];
    const float* bk    = (const float*)d_in[5];
    const float* Wv    = (const float*)d_in[6];
    const float* bv    = (const float*)d_in[7];
    const float* Wout  = (const float*)d_in[8];
    const float* bout  = (const float*)d_in[9];
    const float* gamma = (const float*)d_in[10];
    const float* beta  = (const float*)d_in[11];
    float*       out   = (float*)d_out;

    int N = in_sizes[0] / 3;    // 100000
    int E = in_sizes[1] / 2;    // 500000
    int tot4 = 4 * N;

    setup_kernel<<<2, 576>>>(Wq, bq, Wk, bk, Wv, bv, Wout, ei, E, N);
    zero_kernel<<<(tot4 + 255) / 256, 256>>>(tot4);
    edge_kernel<<<(E + 255) / 256, 256>>>(pos, ei, E, N);
    node_kernel<<<(N * HID + 255) / 256, 256>>>(bout, gamma, beta, out, N);
}

// round 11
// speedup vs baseline: 2.0378x; 1.1490x over previous
#include <cuda_runtime.h>

#define N_MAX   100000
#define HID     32
#define NODE_BLK 256

// Precomputed-parameter layout (floats) in g_P:
//   [0..36)   A[h][i][j]   4 heads x 3x3 score quadratic forms
//   [36..48)  B[h][i]      4 heads x 3   score linear terms
//   [48..52)  C[h]         4 heads       score constants
//   [52..64)  pad
//   [64..576) MM[16][32]   row t=h*4+i : (Wv_h @ Wout_h) rows (i<3), bv_h @ Wout_h (i==3)
#define OFF_A   0
#define OFF_B   36
#define OFF_C   48
#define OFF_MM  64
#define P_SIZE  576
#define P_EDGE  64          // edge kernel only needs A/B/C

__device__ float  g_P[P_SIZE];
__device__ float4 g_wacc[4 * N_MAX];   // [node][head] : (sum aw*rx, aw*ry, aw*rz, aw)
__device__ int    g_idx64;             // 1 if edge_index is int64, 0 if int32

// ---------------------------------------------------------------------------
// Setup (block 0): fold Wq/Wk/bq/bk into per-head 3x3 quadratic score forms,
//                  fold Wv/bv @ Wout into MM[16][32].
// Probe (block 1): decide int64-vs-int32 edge_index in parallel (one pass).
// ---------------------------------------------------------------------------
__global__ void setup_kernel(const float* __restrict__ Wq, const float* __restrict__ bq,
                             const float* __restrict__ Wk, const float* __restrict__ bk,
                             const float* __restrict__ Wv, const float* __restrict__ bv,
                             const float* __restrict__ Wout,
                             const void* __restrict__ ei, int E, int N) {
    int t = threadIdx.x;

    if (blockIdx.x == 1) {
        // ---- parallel dtype probe: 256 lanes each validate one int64 slot ----
        if (t < 256) {
            int n = E < 256 ? E : 256;
            int bad = 0;
            if (t < n) {
                long long v = ((const long long*)ei)[t];
                bad = (v < 0 || v >= (long long)N) ? 1 : 0;
            }
            __shared__ int s_bad;
            if (t == 0) s_bad = 0;
            __syncthreads();
            if (__any_sync(0xffffffffu, bad) && (t & 31) == 0) atomicOr(&s_bad, 1);
            __syncthreads();
            if (t == 0) g_idx64 = s_bad ? 0 : 1;
        }
        return;
    }

    if (t < 512) {
        int row = t >> 5, j = t & 31;
        int h = row >> 2, i = row & 3;
        int base = h * 32;
        float s = 0.f;
        if (i < 3) {
            #pragma unroll 4
            for (int d = 0; d < 32; d++)
                s = fmaf(Wv[i * 128 + base + d], Wout[(base + d) * 32 + j], s);
        } else {
            #pragma unroll 4
            for (int d = 0; d < 32; d++)
                s = fmaf(bv[base + d], Wout[(base + d) * 32 + j], s);
        }
        g_P[OFF_MM + row * 32 + j] = s;
    } else if (t < 548) {
        int a = t - 512;
        int h = a / 9, rem = a % 9;
        int i = rem / 3, j = rem % 3;
        int base = h * 32;
        float s = 0.f;
        for (int d = 0; d < 32; d++)
            s = fmaf(Wq[i * 128 + base + d], Wk[j * 128 + base + d], s);
        g_P[OFF_A + a] = s;
    } else if (t < 560) {
        int a = t - 548;
        int h = a / 3, i = a % 3;
        int base = h * 32;
        float s = 0.f;
        for (int d = 0; d < 32; d++) {
            s = fmaf(Wq[i * 128 + base + d], bk[base + d], s);
            s = fmaf(Wk[i * 128 + base + d], bq[base + d], s);
        }
        g_P[OFF_B + a] = s;
    } else if (t < 564) {
        int h = t - 560;
        int base = h * 32;
        float s = 0.f;
        for (int d = 0; d < 32; d++)
            s = fmaf(bq[base + d], bk[base + d], s);
        g_P[OFF_C + h] = s;
    } else if (t < 576) {
        g_P[52 + (t - 564)] = 0.f;   // pad region
    }
}

// ---------------------------------------------------------------------------
// Zero the node accumulators (every launch), float4-wide.
// ---------------------------------------------------------------------------
__global__ void zero_kernel(int tot4) {
    int i = blockIdx.x * blockDim.x + threadIdx.x;
    if (i < tot4) g_wacc[i] = make_float4(0.f, 0.f, 0.f, 0.f);
}

// ---------------------------------------------------------------------------
// Edge kernel: 1 thread = 1 edge.
//   rel -> 4 head scores (3x3 quadratic forms) -> softmax ->
//   per head one float4 vector red: (attn*rx, attn*ry, attn*rz, attn)
// ---------------------------------------------------------------------------
__global__ void __launch_bounds__(256) edge_kernel(const float* __restrict__ pos,
                                                   const void* __restrict__ ei_raw,
                                                   int E, int N) {
    __shared__ float sP[P_EDGE];
    if (threadIdx.x < P_EDGE) sP[threadIdx.x] = g_P[threadIdx.x];
    __syncthreads();

    int e = blockIdx.x * blockDim.x + threadIdx.x;
    if (e >= E) return;

    int r, c;
    if (g_idx64) {
        const long long* ei = (const long long*)ei_raw;
        r = (int)ei[e];
        c = (int)ei[E + e];
    } else {
        const int* ei = (const int*)ei_raw;
        r = ei[e];
        c = ei[E + e];
    }

    float rx = pos[3 * r + 0] - pos[3 * c + 0];
    float ry = pos[3 * r + 1] - pos[3 * c + 1];
    float rz = pos[3 * r + 2] - pos[3 * c + 2];

    // scores per head: (rel^T A rel + B.rel + C) / sqrt(32)
    float s[4];
    #pragma unroll
    for (int h = 0; h < 4; h++) {
        const float* Ah = sP + OFF_A + h * 9;
        const float* Bh = sP + OFF_B + h * 3;
        float u0 = fmaf(Ah[0], rx, fmaf(Ah[1], ry, fmaf(Ah[2], rz, Bh[0])));
        float u1 = fmaf(Ah[3], rx, fmaf(Ah[4], ry, fmaf(Ah[5], rz, Bh[1])));
        float u2 = fmaf(Ah[6], rx, fmaf(Ah[7], ry, fmaf(Ah[8], rz, Bh[2])));
        s[h] = fmaf(rx, u0, fmaf(ry, u1, fmaf(rz, u2, sP[OFF_C + h])))
               * 0.17677669529663687f;   // 1/sqrt(32)
    }

    // softmax over 4 heads
    float m  = fmaxf(fmaxf(s[0], s[1]), fmaxf(s[2], s[3]));
    float e0 = __expf(s[0] - m);
    float e1 = __expf(s[1] - m);
    float e2 = __expf(s[2] - m);
    float e3 = __expf(s[3] - m);
    float inv = 1.f / (e0 + e1 + e2 + e3);
    float at[4] = {e0 * inv, e1 * inv, e2 * inv, e3 * inv};

    // one 16B hardware vector reduction per head
    float4* base = g_wacc + (size_t)c * 4;
    #pragma unroll
    for (int h = 0; h < 4; h++)
        atomicAdd(base + h, make_float4(at[h] * rx, at[h] * ry, at[h] * rz, at[h]));
}

// ---------------------------------------------------------------------------
// Node kernel: 1 THREAD = 1 node (no shuffles).
//   w16 via 4 coalesced LDG.128, x[32] = (w16@MM)*invc + bout with MM
//   broadcast from SMEM, serial in-register LayerNorm + SiLU, then
//   bank-conflict-free transposed SMEM staging -> coalesced STG.128.
// ---------------------------------------------------------------------------
__global__ void __launch_bounds__(NODE_BLK) node_kernel(const float* __restrict__ bout,
                                                        const float* __restrict__ gamma,
                                                        const float* __restrict__ beta,
                                                        float* __restrict__ out, int N) {
    __shared__ __align__(16) float sMM[512];
    __shared__ float sB[32], sG[32], sBe[32];
    __shared__ float sOut[32 * 257];          // transposed staging, pad 257

    int tid = threadIdx.x;
    for (int t = tid; t < 512; t += NODE_BLK) sMM[t] = g_P[OFF_MM + t];
    if (tid < 32) { sB[tid] = bout[tid]; sG[tid] = gamma[tid]; sBe[tid] = beta[tid]; }
    __syncthreads();

    int n = blockIdx.x * NODE_BLK + tid;
    bool valid = (n < N);

    float4 w0, w1, w2, w3;
    if (valid) {
        const float4* wr = g_wacc + (size_t)n * 4;
        w0 = wr[0]; w1 = wr[1]; w2 = wr[2]; w3 = wr[3];
    } else {
        w0 = w1 = w2 = w3 = make_float4(0.f, 0.f, 0.f, 0.f);
    }
    float w[16] = { w0.x, w0.y, w0.z, w0.w,  w1.x, w1.y, w1.z, w1.w,
                    w2.x, w2.y, w2.z, w2.w,  w3.x, w3.y, w3.z, w3.w };
    float cnt  = w0.w + w1.w + w2.w + w3.w;       // = edge count (softmax sums to 1)
    float invc = 1.f / fmaxf(cnt, 1.f);

    float x[32];
    #pragma unroll
    for (int g = 0; g < 8; g++) {
        float4 a = make_float4(0.f, 0.f, 0.f, 0.f);
        #pragma unroll
        for (int t = 0; t < 16; t++) {
            float4 mv = *reinterpret_cast<const float4*>(sMM + t * 32 + g * 4);
            a.x = fmaf(w[t], mv.x, a.x);
            a.y = fmaf(w[t], mv.y, a.y);
            a.z = fmaf(w[t], mv.z, a.z);
            a.w = fmaf(w[t], mv.w, a.w);
        }
        x[g * 4 + 0] = fmaf(a.x, invc, sB[g * 4 + 0]);
        x[g * 4 + 1] = fmaf(a.y, invc, sB[g * 4 + 1]);
        x[g * 4 + 2] = fmaf(a.z, invc, sB[g * 4 + 2]);
        x[g * 4 + 3] = fmaf(a.w, invc, sB[g * 4 + 3]);
    }

    // in-register LayerNorm
    float mu = 0.f;
    #pragma unroll
    for (int j = 0; j < 32; j++) mu += x[j];
    mu *= 0.03125f;
    float var = 0.f;
    #pragma unroll
    for (int j = 0; j < 32; j++) { float d = x[j] - mu; var = fmaf(d, d, var); }
    float rstd = rsqrtf(fmaf(var, 0.03125f, 1e-5f));

    #pragma unroll
    for (int j = 0; j < 32; j++) {
        float y = fmaf((x[j] - mu) * rstd, sG[j], sBe[j]);
        y = y / (1.f + __expf(-y));               // SiLU
        sOut[j * 257 + tid] = y;                  // transposed, conflict-free
    }
    __syncthreads();

    // coalesced block-wide store of [nvalid][32] floats as float4
    int b0 = blockIdx.x * NODE_BLK;
    int nvalid = N - b0; if (nvalid > NODE_BLK) nvalid = NODE_BLK;
    if (nvalid <= 0) return;
    float4* out4 = reinterpret_cast<float4*>(out) + (size_t)b0 * 8;
    int tot4 = nvalid * 8;
    for (int idx = tid; idx < tot4; idx += NODE_BLK) {
        int node = idx >> 3, grp = idx & 7;
        float4 v;
        v.x = sOut[(grp * 4 + 0) * 257 + node];
        v.y = sOut[(grp * 4 + 1) * 257 + node];
        v.z = sOut[(grp * 4 + 2) * 257 + node];
        v.w = sOut[(grp * 4 + 3) * 257 + node];
        out4[idx] = v;
    }
}

// ---------------------------------------------------------------------------
extern "C" void kernel_launch(void* const* d_in, const int* in_sizes, int n_in,
                              void* d_out, int out_size) {
    const float* pos   = (const float*)d_in[0];
    const void*  ei    = d_in[1];
    const float* Wq    = (const float*)d_in[2];
    const float* bq    = (const float*)d_in[3];
    const float* Wk    = (const float*)d_in[4];
    const float* bk    = (const float*)d_in[5];
    const float* Wv    = (const float*)d_in[6];
    const float* bv    = (const float*)d_in[7];
    const float* Wout  = (const float*)d_in[8];
    const float* bout  = (const float*)d_in[9];
    const float* gamma = (const float*)d_in[10];
    const float* beta  = (const float*)d_in[11];
    float*       out   = (float*)d_out;

    int N = in_sizes[0] / 3;    // 100000
    int E = in_sizes[1] / 2;    // 500000
    int tot4 = 4 * N;

    setup_kernel<<<2, 576>>>(Wq, bq, Wk, bk, Wv, bv, Wout, ei, E, N);
    zero_kernel<<<(tot4 + 255) / 256, 256>>>(tot4);
    edge_kernel<<<(E + 255) / 256, 256>>>(pos, ei, E, N);
    node_kernel<<<(N + NODE_BLK - 1) / NODE_BLK, NODE_BLK>>>(bout, gamma, beta, out, N);
}

// round 12
// speedup vs baseline: 2.0666x; 1.0141x over previous
#include <cuda_runtime.h>

#define N_MAX   100000
#define HID     32
#define NODE_BLK 256

// Precomputed-parameter layout (floats) in g_P:
//   [0..36)   A[h][i][j]   4 heads x 3x3 score quadratic forms
//   [36..48)  B[h][i]      4 heads x 3   score linear terms
//   [48..52)  C[h]         4 heads       score constants
//   [52..64)  pad
//   [64..576) MM[16][32]   row t=h*4+i : (Wv_h @ Wout_h) rows (i<3), bv_h @ Wout_h (i==3)
#define OFF_A   0
#define OFF_B   36
#define OFF_C   48
#define OFF_MM  64
#define P_SIZE  576
#define P_EDGE  64          // edge kernel only needs A/B/C

__device__ float  g_P[P_SIZE];
__device__ float4 g_wacc[4 * N_MAX];   // [node][head] : (sum aw*rx, aw*ry, aw*rz, aw)
__device__ int    g_idx64;             // 1 if edge_index is int64, 0 if int32

// ---------------------------------------------------------------------------
// Setup (block 0): fold Wq/Wk/bq/bk into per-head 3x3 quadratic score forms,
//                  fold Wv/bv @ Wout into MM[16][32].
// Probe (block 1): decide int64-vs-int32 edge_index in parallel (one pass).
// ---------------------------------------------------------------------------
__global__ void setup_kernel(const float* __restrict__ Wq, const float* __restrict__ bq,
                             const float* __restrict__ Wk, const float* __restrict__ bk,
                             const float* __restrict__ Wv, const float* __restrict__ bv,
                             const float* __restrict__ Wout,
                             const void* __restrict__ ei, int E, int N) {
    int t = threadIdx.x;

    if (blockIdx.x == 1) {
        // ---- parallel dtype probe: 256 lanes each validate one int64 slot ----
        if (t < 256) {
            int n = E < 256 ? E : 256;
            int bad = 0;
            if (t < n) {
                long long v = ((const long long*)ei)[t];
                bad = (v < 0 || v >= (long long)N) ? 1 : 0;
            }
            __shared__ int s_bad;
            if (t == 0) s_bad = 0;
            __syncthreads();
            if (__any_sync(0xffffffffu, bad) && (t & 31) == 0) atomicOr(&s_bad, 1);
            __syncthreads();
            if (t == 0) g_idx64 = s_bad ? 0 : 1;
        }
        return;
    }

    if (t < 512) {
        int row = t >> 5, j = t & 31;
        int h = row >> 2, i = row & 3;
        int base = h * 32;
        float s = 0.f;
        if (i < 3) {
            #pragma unroll 4
            for (int d = 0; d < 32; d++)
                s = fmaf(Wv[i * 128 + base + d], Wout[(base + d) * 32 + j], s);
        } else {
            #pragma unroll 4
            for (int d = 0; d < 32; d++)
                s = fmaf(bv[base + d], Wout[(base + d) * 32 + j], s);
        }
        g_P[OFF_MM + row * 32 + j] = s;
    } else if (t < 548) {
        int a = t - 512;
        int h = a / 9, rem = a % 9;
        int i = rem / 3, j = rem % 3;
        int base = h * 32;
        float s = 0.f;
        for (int d = 0; d < 32; d++)
            s = fmaf(Wq[i * 128 + base + d], Wk[j * 128 + base + d], s);
        g_P[OFF_A + a] = s;
    } else if (t < 560) {
        int a = t - 548;
        int h = a / 3, i = a % 3;
        int base = h * 32;
        float s = 0.f;
        for (int d = 0; d < 32; d++) {
            s = fmaf(Wq[i * 128 + base + d], bk[base + d], s);
            s = fmaf(Wk[i * 128 + base + d], bq[base + d], s);
        }
        g_P[OFF_B + a] = s;
    } else if (t < 564) {
        int h = t - 560;
        int base = h * 32;
        float s = 0.f;
        for (int d = 0; d < 32; d++)
            s = fmaf(bq[base + d], bk[base + d], s);
        g_P[OFF_C + h] = s;
    } else if (t < 576) {
        g_P[52 + (t - 564)] = 0.f;   // pad region
    }
}

// ---------------------------------------------------------------------------
// Zero the node accumulators (every launch), float4-wide.
// ---------------------------------------------------------------------------
__global__ void zero_kernel(int tot4) {
    int i = blockIdx.x * blockDim.x + threadIdx.x;
    if (i < tot4) g_wacc[i] = make_float4(0.f, 0.f, 0.f, 0.f);
}

// ---------------------------------------------------------------------------
// Edge kernel: 1 thread = 1 edge.
//   rel -> 4 head scores (3x3 quadratic forms) -> softmax ->
//   per head one float4 vector red: (attn*rx, attn*ry, attn*rz, attn)
// ---------------------------------------------------------------------------
__global__ void __launch_bounds__(256) edge_kernel(const float* __restrict__ pos,
                                                   const void* __restrict__ ei_raw,
                                                   int E, int N) {
    __shared__ float sP[P_EDGE];
    if (threadIdx.x < P_EDGE) sP[threadIdx.x] = g_P[threadIdx.x];
    __syncthreads();

    int e = blockIdx.x * blockDim.x + threadIdx.x;
    if (e >= E) return;

    int r, c;
    if (g_idx64) {
        const long long* ei = (const long long*)ei_raw;
        r = (int)ei[e];
        c = (int)ei[E + e];
    } else {
        const int* ei = (const int*)ei_raw;
        r = ei[e];
        c = ei[E + e];
    }

    float rx = pos[3 * r + 0] - pos[3 * c + 0];
    float ry = pos[3 * r + 1] - pos[3 * c + 1];
    float rz = pos[3 * r + 2] - pos[3 * c + 2];

    // scores per head: (rel^T A rel + B.rel + C) / sqrt(32)
    float s[4];
    #pragma unroll
    for (int h = 0; h < 4; h++) {
        const float* Ah = sP + OFF_A + h * 9;
        const float* Bh = sP + OFF_B + h * 3;
        float u0 = fmaf(Ah[0], rx, fmaf(Ah[1], ry, fmaf(Ah[2], rz, Bh[0])));
        float u1 = fmaf(Ah[3], rx, fmaf(Ah[4], ry, fmaf(Ah[5], rz, Bh[1])));
        float u2 = fmaf(Ah[6], rx, fmaf(Ah[7], ry, fmaf(Ah[8], rz, Bh[2])));
        s[h] = fmaf(rx, u0, fmaf(ry, u1, fmaf(rz, u2, sP[OFF_C + h])))
               * 0.17677669529663687f;   // 1/sqrt(32)
    }

    // softmax over 4 heads
    float m  = fmaxf(fmaxf(s[0], s[1]), fmaxf(s[2], s[3]));
    float e0 = __expf(s[0] - m);
    float e1 = __expf(s[1] - m);
    float e2 = __expf(s[2] - m);
    float e3 = __expf(s[3] - m);
    float inv = 1.f / (e0 + e1 + e2 + e3);
    float at[4] = {e0 * inv, e1 * inv, e2 * inv, e3 * inv};

    // one 16B hardware vector reduction per head
    float4* base = g_wacc + (size_t)c * 4;
    #pragma unroll
    for (int h = 0; h < 4; h++)
        atomicAdd(base + h, make_float4(at[h] * rx, at[h] * ry, at[h] * rz, at[h]));
}

// ---------------------------------------------------------------------------
// Node kernel: 8 THREADS per node (thread = one 4-channel group).
//   All 8 threads of a node load the same 64B w-row (L1 broadcast).
//   x[4] = (w16 . MM[:, g*4..g*4+3]) * invc + bout; LN reduction over the
//   8-lane group via shfl_xor 1/2/4; store = naturally coalesced STG.128.
// ---------------------------------------------------------------------------
__global__ void __launch_bounds__(NODE_BLK) node_kernel(const float* __restrict__ bout,
                                                        const float* __restrict__ gamma,
                                                        const float* __restrict__ beta,
                                                        float* __restrict__ out, int N) {
    __shared__ __align__(16) float sMM[512];
    __shared__ float sB[32], sG[32], sBe[32];

    int tid = threadIdx.x;
    for (int t = tid; t < 512; t += NODE_BLK) sMM[t] = g_P[OFF_MM + t];
    if (tid < 32) { sB[tid] = bout[tid]; sG[tid] = gamma[tid]; sBe[tid] = beta[tid]; }
    __syncthreads();

    int gt = blockIdx.x * NODE_BLK + tid;
    int n  = gt >> 3;          // node
    int g  = gt & 7;           // channel group (4 channels)
    if (n >= N) return;

    const float4* wr = g_wacc + (size_t)n * 4;
    float4 w0 = wr[0], w1 = wr[1], w2 = wr[2], w3 = wr[3];
    float w[16] = { w0.x, w0.y, w0.z, w0.w,  w1.x, w1.y, w1.z, w1.w,
                    w2.x, w2.y, w2.z, w2.w,  w3.x, w3.y, w3.z, w3.w };
    float cnt  = w0.w + w1.w + w2.w + w3.w;       // = edge count (softmax sums to 1)
    float invc = 1.f / fmaxf(cnt, 1.f);

    float4 a = make_float4(0.f, 0.f, 0.f, 0.f);
    #pragma unroll
    for (int t = 0; t < 16; t++) {
        float4 mv = *reinterpret_cast<const float4*>(sMM + t * 32 + g * 4);
        a.x = fmaf(w[t], mv.x, a.x);
        a.y = fmaf(w[t], mv.y, a.y);
        a.z = fmaf(w[t], mv.z, a.z);
        a.w = fmaf(w[t], mv.w, a.w);
    }
    int j0 = g * 4;
    float x0 = fmaf(a.x, invc, sB[j0 + 0]);
    float x1 = fmaf(a.y, invc, sB[j0 + 1]);
    float x2 = fmaf(a.z, invc, sB[j0 + 2]);
    float x3 = fmaf(a.w, invc, sB[j0 + 3]);

    // LayerNorm over the node's 32 channels: reduce across the 8-lane group
    float ps = x0 + x1 + x2 + x3;
    #pragma unroll
    for (int o = 4; o; o >>= 1) ps += __shfl_xor_sync(0xffffffffu, ps, o);
    float mu = ps * 0.03125f;

    float d0 = x0 - mu, d1 = x1 - mu, d2 = x2 - mu, d3 = x3 - mu;
    float pv = fmaf(d0, d0, fmaf(d1, d1, fmaf(d2, d2, d3 * d3)));
    #pragma unroll
    for (int o = 4; o; o >>= 1) pv += __shfl_xor_sync(0xffffffffu, pv, o);
    float rstd = rsqrtf(fmaf(pv, 0.03125f, 1e-5f));

    float4 y;
    y.x = fmaf(d0 * rstd, sG[j0 + 0], sBe[j0 + 0]);
    y.y = fmaf(d1 * rstd, sG[j0 + 1], sBe[j0 + 1]);
    y.z = fmaf(d2 * rstd, sG[j0 + 2], sBe[j0 + 2]);
    y.w = fmaf(d3 * rstd, sG[j0 + 3], sBe[j0 + 3]);
    y.x = y.x / (1.f + __expf(-y.x));
    y.y = y.y / (1.f + __expf(-y.y));
    y.z = y.z / (1.f + __expf(-y.z));
    y.w = y.w / (1.f + __expf(-y.w));

    reinterpret_cast<float4*>(out)[gt] = y;   // consecutive threads -> coalesced
}

// ---------------------------------------------------------------------------
extern "C" void kernel_launch(void* const* d_in, const int* in_sizes, int n_in,
                              void* d_out, int out_size) {
    const float* pos   = (const float*)d_in[0];
    const void*  ei    = d_in[1];
    const float* Wq    = (const float*)d_in[2];
    const float* bq    = (const float*)d_in[3];
    const float* Wk    = (const float*)d_in[4];
    const float* bk    = (const float*)d_in[5];
    const float* Wv    = (const float*)d_in[6];
    const float* bv    = (const float*)d_in[7];
    const float* Wout  = (const float*)d_in[8];
    const float* bout  = (const float*)d_in[9];
    const float* gamma = (const float*)d_in[10];
    const float* beta  = (const float*)d_in[11];
    float*       out   = (float*)d_out;

    int N = in_sizes[0] / 3;    // 100000
    int E = in_sizes[1] / 2;    // 500000
    int tot4 = 4 * N;

    setup_kernel<<<2, 576>>>(Wq, bq, Wk, bk, Wv, bv, Wout, ei, E, N);
    zero_kernel<<<(tot4 + 255) / 256, 256>>>(tot4);
    edge_kernel<<<(E + 255) / 256, 256>>>(pos, ei, E, N);
    node_kernel<<<(8 * N + NODE_BLK - 1) / NODE_BLK, NODE_BLK>>>(bout, gamma, beta, out, N);
}

// round 16
// speedup vs baseline: 2.3904x; 1.1567x over previous
#include <cuda_runtime.h>

#define N_MAX   100000
#define HID     32
#define NODE_BLK 256
#define SETUP_BLK 576

// Precomputed-parameter layout (floats) in g_P:
//   [0..36)   A[h][i][j]   4 heads x 3x3 score quadratic forms
//   [36..48)  B[h][i]      4 heads x 3   score linear terms
//   [48..52)  C[h]         4 heads       score constants
//   [52..64)  pad
//   [64..576) MM[16][32]   row t=h*4+i : (Wv_h @ Wout_h) rows (i<3), bv_h @ Wout_h (i==3)
#define OFF_A   0
#define OFF_B   36
#define OFF_C   48
#define OFF_MM  64
#define P_SIZE  576
#define P_EDGE  64          // edge kernel only needs A/B/C

__device__ float  g_P[P_SIZE];
__device__ float4 g_wacc[4 * N_MAX];   // [node][head] : (sum aw*rx, aw*ry, aw*rz, aw)
__device__ int    g_idx64;             // 1 if edge_index is int64, 0 if int32

// ---------------------------------------------------------------------------
// Setup (block 0): fold weights. Probe (block 1): int64-vs-int32 edge_index.
// Blocks >= 2: zero the float4 node accumulators (fused former zero_kernel).
// ---------------------------------------------------------------------------
__global__ void setup_kernel(const float* __restrict__ Wq, const float* __restrict__ bq,
                             const float* __restrict__ Wk, const float* __restrict__ bk,
                             const float* __restrict__ Wv, const float* __restrict__ bv,
                             const float* __restrict__ Wout,
                             const void* __restrict__ ei, int E, int N) {
    int t = threadIdx.x;

    if (blockIdx.x >= 2) {
        int i = (blockIdx.x - 2) * SETUP_BLK + t;
        if (i < 4 * N) g_wacc[i] = make_float4(0.f, 0.f, 0.f, 0.f);
        return;
    }

    if (blockIdx.x == 1) {
        // ---- parallel dtype probe: 256 lanes each validate one int64 slot ----
        if (t < 256) {
            int n = E < 256 ? E : 256;
            int bad = 0;
            if (t < n) {
                long long v = ((const long long*)ei)[t];
                bad = (v < 0 || v >= (long long)N) ? 1 : 0;
            }
            __shared__ int s_bad;
            if (t == 0) s_bad = 0;
            __syncthreads();
            if (__any_sync(0xffffffffu, bad) && (t & 31) == 0) atomicOr(&s_bad, 1);
            __syncthreads();
            if (t == 0) g_idx64 = s_bad ? 0 : 1;
        }
        return;
    }

    if (t < 512) {
        int row = t >> 5, j = t & 31;
        int h = row >> 2, i = row & 3;
        int base = h * 32;
        float s = 0.f;
        if (i < 3) {
            #pragma unroll 4
            for (int d = 0; d < 32; d++)
                s = fmaf(Wv[i * 128 + base + d], Wout[(base + d) * 32 + j], s);
        } else {
            #pragma unroll 4
            for (int d = 0; d < 32; d++)
                s = fmaf(bv[base + d], Wout[(base + d) * 32 + j], s);
        }
        g_P[OFF_MM + row * 32 + j] = s;
    } else if (t < 548) {
        int a = t - 512;
        int h = a / 9, rem = a % 9;
        int i = rem / 3, j = rem % 3;
        int base = h * 32;
        float s = 0.f;
        for (int d = 0; d < 32; d++)
            s = fmaf(Wq[i * 128 + base + d], Wk[j * 128 + base + d], s);
        g_P[OFF_A + a] = s;
    } else if (t < 560) {
        int a = t - 548;
        int h = a / 3, i = a % 3;
        int base = h * 32;
        float s = 0.f;
        for (int d = 0; d < 32; d++) {
            s = fmaf(Wq[i * 128 + base + d], bk[base + d], s);
            s = fmaf(Wk[i * 128 + base + d], bq[base + d], s);
        }
        g_P[OFF_B + a] = s;
    } else if (t < 564) {
        int h = t - 560;
        int base = h * 32;
        float s = 0.f;
        for (int d = 0; d < 32; d++)
            s = fmaf(bq[base + d], bk[base + d], s);
        g_P[OFF_C + h] = s;
    } else if (t < 576) {
        g_P[52 + (t - 564)] = 0.f;   // pad region
    }
}

// ---------------------------------------------------------------------------
// Edge kernel: 1 thread = 1 edge.
//   rel -> 4 head scores (3x3 quadratic forms) -> softmax ->
//   per head one float4 vector red: (attn*rx, attn*ry, attn*rz, attn)
// ---------------------------------------------------------------------------
__global__ void __launch_bounds__(256) edge_kernel(const float* __restrict__ pos,
                                                   const void* __restrict__ ei_raw,
                                                   int E, int N) {
    __shared__ float sP[P_EDGE];
    if (threadIdx.x < P_EDGE) sP[threadIdx.x] = g_P[threadIdx.x];
    __syncthreads();

    int e = blockIdx.x * blockDim.x + threadIdx.x;
    if (e >= E) return;

    int r, c;
    if (g_idx64) {
        const long long* ei = (const long long*)ei_raw;
        r = (int)ei[e];
        c = (int)ei[E + e];
    } else {
        const int* ei = (const int*)ei_raw;
        r = ei[e];
        c = ei[E + e];
    }

    float rx = pos[3 * r + 0] - pos[3 * c + 0];
    float ry = pos[3 * r + 1] - pos[3 * c + 1];
    float rz = pos[3 * r + 2] - pos[3 * c + 2];

    // scores per head: (rel^T A rel + B.rel + C) / sqrt(32)
    float s[4];
    #pragma unroll
    for (int h = 0; h < 4; h++) {
        const float* Ah = sP + OFF_A + h * 9;
        const float* Bh = sP + OFF_B + h * 3;
        float u0 = fmaf(Ah[0], rx, fmaf(Ah[1], ry, fmaf(Ah[2], rz, Bh[0])));
        float u1 = fmaf(Ah[3], rx, fmaf(Ah[4], ry, fmaf(Ah[5], rz, Bh[1])));
        float u2 = fmaf(Ah[6], rx, fmaf(Ah[7], ry, fmaf(Ah[8], rz, Bh[2])));
        s[h] = fmaf(rx, u0, fmaf(ry, u1, fmaf(rz, u2, sP[OFF_C + h])))
               * 0.17677669529663687f;   // 1/sqrt(32)
    }

    // softmax over 4 heads
    float m  = fmaxf(fmaxf(s[0], s[1]), fmaxf(s[2], s[3]));
    float e0 = __expf(s[0] - m);
    float e1 = __expf(s[1] - m);
    float e2 = __expf(s[2] - m);
    float e3 = __expf(s[3] - m);
    float inv = 1.f / (e0 + e1 + e2 + e3);
    float at[4] = {e0 * inv, e1 * inv, e2 * inv, e3 * inv};

    // one 16B hardware vector reduction per head
    float4* base = g_wacc + (size_t)c * 4;
    #pragma unroll
    for (int h = 0; h < 4; h++)
        atomicAdd(base + h, make_float4(at[h] * rx, at[h] * ry, at[h] * rz, at[h]));
}

// ---------------------------------------------------------------------------
// Node kernel: thread = (channel-group g, node PAIR). Each LDS.128 of MM
// feeds FMAs for TWO nodes -> smem phases per node halved vs 1-node/thread.
// 8 consecutive lanes hold both nodes of the pair; LN reductions via
// shfl_xor 1/2/4 within the 8-lane group. Stores coalesced STG.128.
// ---------------------------------------------------------------------------
__global__ void __launch_bounds__(NODE_BLK) node_kernel(const float* __restrict__ bout,
                                                        const float* __restrict__ gamma,
                                                        const float* __restrict__ beta,
                                                        float* __restrict__ out, int N) {
    __shared__ __align__(16) float sMM[512];
    __shared__ float sB[32], sG[32], sBe[32];

    int tid = threadIdx.x;
    for (int t = tid; t < 512; t += NODE_BLK) sMM[t] = g_P[OFF_MM + t];
    if (tid < 32) { sB[tid] = bout[tid]; sG[tid] = gamma[tid]; sBe[tid] = beta[tid]; }
    __syncthreads();

    int gt   = blockIdx.x * NODE_BLK + tid;   // [0, 4N)
    int pair = gt >> 3;                        // node pair index
    int g    = gt & 7;                         // channel group (4 channels)
    int n0   = pair * 2;
    int n1   = n0 + 1;
    if (n0 >= N) return;
    bool has1 = (n1 < N);

    const float4* wr0 = g_wacc + (size_t)n0 * 4;
    float4 a0_ = wr0[0], b0_ = wr0[1], c0_ = wr0[2], d0_ = wr0[3];
    float4 a1_, b1_, c1_, d1_;
    if (has1) {
        const float4* wr1 = g_wacc + (size_t)n1 * 4;
        a1_ = wr1[0]; b1_ = wr1[1]; c1_ = wr1[2]; d1_ = wr1[3];
    } else {
        a1_ = b1_ = c1_ = d1_ = make_float4(0.f, 0.f, 0.f, 0.f);
    }
    float w0[16] = { a0_.x,a0_.y,a0_.z,a0_.w, b0_.x,b0_.y,b0_.z,b0_.w,
                     c0_.x,c0_.y,c0_.z,c0_.w, d0_.x,d0_.y,d0_.z,d0_.w };
    float w1[16] = { a1_.x,a1_.y,a1_.z,a1_.w, b1_.x,b1_.y,b1_.z,b1_.w,
                     c1_.x,c1_.y,c1_.z,c1_.w, d1_.x,d1_.y,d1_.z,d1_.w };
    float invc0 = 1.f / fmaxf(a0_.w + b0_.w + c0_.w + d0_.w, 1.f);
    float invc1 = 1.f / fmaxf(a1_.w + b1_.w + c1_.w + d1_.w, 1.f);

    float4 acc0 = make_float4(0.f, 0.f, 0.f, 0.f);
    float4 acc1 = make_float4(0.f, 0.f, 0.f, 0.f);
    #pragma unroll
    for (int t = 0; t < 16; t++) {
        float4 mv = *reinterpret_cast<const float4*>(sMM + t * 32 + g * 4);
        acc0.x = fmaf(w0[t], mv.x, acc0.x);  acc1.x = fmaf(w1[t], mv.x, acc1.x);
        acc0.y = fmaf(w0[t], mv.y, acc0.y);  acc1.y = fmaf(w1[t], mv.y, acc1.y);
        acc0.z = fmaf(w0[t], mv.z, acc0.z);  acc1.z = fmaf(w1[t], mv.z, acc1.z);
        acc0.w = fmaf(w0[t], mv.w, acc0.w);  acc1.w = fmaf(w1[t], mv.w, acc1.w);
    }

    int j0 = g * 4;
    float bj0 = sB[j0], bj1 = sB[j0 + 1], bj2 = sB[j0 + 2], bj3 = sB[j0 + 3];
    float x00 = fmaf(acc0.x, invc0, bj0), x01 = fmaf(acc0.y, invc0, bj1);
    float x02 = fmaf(acc0.z, invc0, bj2), x03 = fmaf(acc0.w, invc0, bj3);
    float x10 = fmaf(acc1.x, invc1, bj0), x11 = fmaf(acc1.y, invc1, bj1);
    float x12 = fmaf(acc1.z, invc1, bj2), x13 = fmaf(acc1.w, invc1, bj3);

    // LN reductions across the 8-lane group, both nodes at once
    float ps0 = x00 + x01 + x02 + x03;
    float ps1 = x10 + x11 + x12 + x13;
    #pragma unroll
    for (int o = 4; o; o >>= 1) {
        ps0 += __shfl_xor_sync(0xffffffffu, ps0, o);
        ps1 += __shfl_xor_sync(0xffffffffu, ps1, o);
    }
    float mu0 = ps0 * 0.03125f, mu1 = ps1 * 0.03125f;

    float e00 = x00 - mu0, e01 = x01 - mu0, e02 = x02 - mu0, e03 = x03 - mu0;
    float e10 = x10 - mu1, e11 = x11 - mu1, e12 = x12 - mu1, e13 = x13 - mu1;
    float pv0 = fmaf(e00, e00, fmaf(e01, e01, fmaf(e02, e02, e03 * e03)));
    float pv1 = fmaf(e10, e10, fmaf(e11, e11, fmaf(e12, e12, e13 * e13)));
    #pragma unroll
    for (int o = 4; o; o >>= 1) {
        pv0 += __shfl_xor_sync(0xffffffffu, pv0, o);
        pv1 += __shfl_xor_sync(0xffffffffu, pv1, o);
    }
    float rs0 = rsqrtf(fmaf(pv0, 0.03125f, 1e-5f));
    float rs1 = rsqrtf(fmaf(pv1, 0.03125f, 1e-5f));

    float gj0 = sG[j0], gj1 = sG[j0 + 1], gj2 = sG[j0 + 2], gj3 = sG[j0 + 3];
    float t0 = sBe[j0], t1 = sBe[j0 + 1], t2 = sBe[j0 + 2], t3 = sBe[j0 + 3];

    float4 y0, y1;
    y0.x = fmaf(e00 * rs0, gj0, t0);  y0.y = fmaf(e01 * rs0, gj1, t1);
    y0.z = fmaf(e02 * rs0, gj2, t2);  y0.w = fmaf(e03 * rs0, gj3, t3);
    y1.x = fmaf(e10 * rs1, gj0, t0);  y1.y = fmaf(e11 * rs1, gj1, t1);
    y1.z = fmaf(e12 * rs1, gj2, t2);  y1.w = fmaf(e13 * rs1, gj3, t3);
    y0.x /= (1.f + __expf(-y0.x));  y0.y /= (1.f + __expf(-y0.y));
    y0.z /= (1.f + __expf(-y0.z));  y0.w /= (1.f + __expf(-y0.w));
    y1.x /= (1.f + __expf(-y1.x));  y1.y /= (1.f + __expf(-y1.y));
    y1.z /= (1.f + __expf(-y1.z));  y1.w /= (1.f + __expf(-y1.w));

    float4* out4 = reinterpret_cast<float4*>(out);
    out4[(size_t)n0 * 8 + g] = y0;
    if (has1) out4[(size_t)n1 * 8 + g] = y1;
}

// ---------------------------------------------------------------------------
extern "C" void kernel_launch(void* const* d_in, const int* in_sizes, int n_in,
                              void* d_out, int out_size) {
    const float* pos   = (const float*)d_in[0];
    const void*  ei    = d_in[1];
    const float* Wq    = (const float*)d_in[2];
    const float* bq    = (const float*)d_in[3];
    const float* Wk    = (const float*)d_in[4];
    const float* bk    = (const float*)d_in[5];
    const float* Wv    = (const float*)d_in[6];
    const float* bv    = (const float*)d_in[7];
    const float* Wout  = (const float*)d_in[8];
    const float* bout  = (const float*)d_in[9];
    const float* gamma = (const float*)d_in[10];
    const float* beta  = (const float*)d_in[11];
    float*       out   = (float*)d_out;

    int N = in_sizes[0] / 3;    // 100000
    int E = in_sizes[1] / 2;    // 500000
    int tot4 = 4 * N;

    int zero_blks = (tot4 + SETUP_BLK - 1) / SETUP_BLK;
    setup_kernel<<<2 + zero_blks, SETUP_BLK>>>(Wq, bq, Wk, bk, Wv, bv, Wout, ei, E, N);
    edge_kernel<<<(E + 255) / 256, 256>>>(pos, ei, E, N);
    node_kernel<<<(4 * N + NODE_BLK - 1) / NODE_BLK, NODE_BLK>>>(bout, gamma, beta, out, N);
}